// round 16
// baseline (speedup 1.0000x reference)
#include <cuda_runtime.h>
#include <cuda_fp16.h>
#include <cstdint>

#define DIN 448
#define HEADS 8
#define HD 56
#define SEQ 8192
#define TOKENS 65536
#define NSLOT 37                      // CTAs per head; grid = 8*37 = 296 = 2/SM
#define MTILES 256                    // 65536 / 256
#define NKT    7                      // 448 / 64
#define GBK    64                     // k-tile depth (halves)

// ---------------- scratch (device globals; no runtime alloc) ---------------
__device__ __half Eh_g[DIN * DIN];
__device__ __half Wh_g[DIN * DIN];
__device__ uint4  Yb_g[(size_t)TOKENS * DIN / 8];   // Yn blob (fp16)

// Blob mapping for a [rows, 448] fp16 matrix:
//   row: mi=row>>8, rt=row&255, w=rt>>6, mt=(rt>>4)&3, hi=(rt>>3)&1, g=rt&7
//   col: kt=col>>6, kk=(col>>4)&3, li=(col>>2)&3, p=col&3
//   uint4 index = ((mi*7+kt)*16 + w*4 + kk)*128 + mt*32 + g*4 + li
//   16B unit = MMA regs {a0,a1,a2,a3} under the phys-col relabel
//   hw{2li,2li+1}->4li,4li+1 ; hw{2li+8,2li+9}->4li+2,4li+3
//   (same relabel applied to B fragments -> contraction exact).

// ---------------- helpers --------------------------------------------------
#define CP_ASYNC16(dst, src) \
    asm volatile("cp.async.cg.shared.global [%0], [%1], 16;" :: "r"(dst), "l"(src) : "memory")
#define CP_COMMIT() asm volatile("cp.async.commit_group;" ::: "memory")
#define CP_WAIT0()  asm volatile("cp.async.wait_group 0;" ::: "memory")
#define PREFETCH_L2(p) \
    asm volatile("prefetch.global.L2 [%0];" :: "l"(p))

__device__ __forceinline__ uint32_t smem_u32(const void* p) {
    uint32_t a;
    asm("{ .reg .u64 t; cvta.to.shared.u64 t, %1; cvt.u32.u64 %0, t; }"
        : "=r"(a) : "l"(p));
    return a;
}
__device__ __forceinline__ uint4 packfrag(float4 a, float4 b) {
    __half2 h0 = __floats2half2_rn(a.x, a.y);   // row g,   p01
    __half2 h1 = __floats2half2_rn(b.x, b.y);   // row g+8, p01
    __half2 h2 = __floats2half2_rn(a.z, a.w);   // row g,   p23
    __half2 h3 = __floats2half2_rn(b.z, b.w);   // row g+8, p23
    uint4 o;
    o.x = *(uint32_t*)&h0; o.y = *(uint32_t*)&h1;
    o.z = *(uint32_t*)&h2; o.w = *(uint32_t*)&h3;
    return o;
}

#define B_CHUNK (HD * 128)               // 7168 per k-tile
#define GSMEM   (NKT * B_CHUNK)          // 50176
#define KT_U4   2048                     // uint4 per (mi,kt) blob block

#define MMA_FP16(acc, a, bv)                                                  \
    asm volatile(                                                             \
        "mma.sync.aligned.m16n8k16.row.col.f32.f16.f16.f32 "                  \
        "{%0,%1,%2,%3}, {%4,%5,%6,%7}, {%8,%9}, {%0,%1,%2,%3};\n"             \
        : "+f"((acc)[0]), "+f"((acc)[1]), "+f"((acc)[2]), "+f"((acc)[3])      \
        : "r"((a).x), "r"((a).y), "r"((a).z), "r"((a).w),                     \
          "r"((bv).x), "r"((bv).y))

// ============================================================================
// GEMM1 (fused): Y = x[f32] @ E^T, LayerNorm over permuted rows -> Yn blob.
// A read DIRECTLY from f32 x; fragments converted to fp16 at ring refill.
// B (56x448, one head) resident in smem. 4 warps, warp tile 64x56. 2 CTAs/SM.
// ============================================================================
__global__ __launch_bounds__(128, 2) void gemm1_f32(
    const float* __restrict__ X,     // [65536, 448] f32 row-major
    const __half* __restrict__ Bg,   // E [448,448] row-major [n,k] fp16
    uint4* __restrict__ Og,          // Yn blob
    const float* __restrict__ g1,    // gamma
    const float* __restrict__ g2)    // beta
{
    extern __shared__ char sm[];
    const uint32_t sb = smem_u32(sm);
    const int tid  = threadIdx.x;
    const int warp = tid >> 5, lane = tid & 31;
    const int g  = lane >> 2, li = lane & 3;
    const int hh   = blockIdx.x & 7;
    const int slot = blockIdx.x >> 3;
    const int N0 = hh * HD;
    const int ntile = (slot + NSLOT * 6 < MTILES) ? 7 : 6;

    uint32_t brow[7], swk[4];
    #pragma unroll
    for (int nt = 0; nt < 7; nt++) brow[nt] = (uint32_t)((nt * 8 + g) * 128);
    #pragma unroll
    for (int kk = 0; kk < 4; kk++)
        swk[kk] = (uint32_t)((((2 * kk + (li >> 1)) ^ g) << 4) | ((li & 1) << 3));

    // thread-const f32 row offset within a tile: (warp*64+g)*448 + li*4
    const uint32_t lrow = (uint32_t)((warp * 64 + g) * DIN + li * 4);

    // ---- B panel -> smem (once) ----
    #pragma unroll
    for (int j = 0; j < 25; j++) {
        int o = tid + 128 * j;
        if (o < NKT * HD * 8) {
            int kt = o / (HD * 8), rem = o % (HD * 8);
            int row = rem >> 3, c2 = rem & 7;
            CP_ASYNC16(sb + kt * B_CHUNK + (uint32_t)row * 128
                           + ((uint32_t)((c2 ^ (row & 7)) << 4)),
                       Bg + (size_t)(N0 + row) * DIN + (size_t)kt * GBK + c2 * 8);
        }
    }
    CP_COMMIT();

    // ---- prologue: first k-tile's A fragments (convert f32 -> fp16) ----
    uint4 frag[4][4];
    {
        const float* xt = X + (size_t)slot * 256 * DIN + lrow;
        #pragma unroll
        for (int kk = 0; kk < 4; kk++)
            #pragma unroll
            for (int mt = 0; mt < 4; mt++) {
                const float* p = xt + mt * 16 * DIN + kk * 16;
                frag[kk][mt] = packfrag(*(const float4*)p,
                                        *(const float4*)(p + 8 * DIN));
            }
    }

    CP_WAIT0();
    __syncthreads();                      // B visible; only barrier in kernel

    float acc[4][7][4];
    #pragma unroll
    for (int mt = 0; mt < 4; mt++)
        #pragma unroll
        for (int nt = 0; nt < 7; nt++)
            #pragma unroll
            for (int r = 0; r < 4; r++) acc[mt][nt][r] = 0.f;

    int mi = slot;
    for (int ti = 0; ti < ntile; ti++) {
        for (int kt = 0; kt < NKT; kt++) {
            const char* sbp = sm + kt * B_CHUNK;
            const bool more = (kt < NKT - 1) || (ti < ntile - 1);
            const int nmi = (kt < NKT - 1) ? mi : mi + NSLOT;
            const int nkt = (kt < NKT - 1) ? kt + 1 : 0;
            const float* xn = X + (size_t)nmi * 256 * DIN + lrow + nkt * GBK;

            // L2 prefetch: x region for k-tile t+2 (2 rows x 2 lines / thread)
            {
                int p2mi, p2kt;
                bool pok = true;
                if (kt + 2 < NKT)        { p2mi = mi;         p2kt = kt + 2; }
                else if (ti + 1 < ntile) { p2mi = mi + NSLOT; p2kt = kt + 2 - NKT; }
                else                     { p2mi = mi; p2kt = 0; pok = false; }
                if (pok) {
                    const char* pp = (const char*)(X
                        + ((size_t)p2mi * 256 + 2 * tid) * DIN + p2kt * GBK);
                    PREFETCH_L2(pp);        PREFETCH_L2(pp + 128);
                    PREFETCH_L2(pp + 1792); PREFETCH_L2(pp + 1920);
                }
            }

            #pragma unroll
            for (int kk = 0; kk < 4; kk++) {
                const uint32_t sw = swk[kk];
                uint2 bv[7];
                #pragma unroll
                for (int nt = 0; nt < 7; nt++)
                    bv[nt] = *(const uint2*)(sbp + brow[nt] + sw);
                #pragma unroll
                for (int mt = 0; mt < 4; mt++) {
                    const uint4 a = frag[kk][mt];
                    #pragma unroll
                    for (int nt = 0; nt < 7; nt++)
                        MMA_FP16(acc[mt][nt], a, bv[nt]);
                }
                if (more) {   // refill ring slot from f32 x (convert now)
                    #pragma unroll
                    for (int mt = 0; mt < 4; mt++) {
                        const float* p = xn + mt * 16 * DIN + kk * 16;
                        frag[kk][mt] = packfrag(*(const float4*)p,
                                                *(const float4*)(p + 8 * DIN));
                    }
                }
            }
        }

        // ---- LN epilogue for m-tile mi -> Yn blob ----
        #pragma unroll
        for (int mt = 0; mt < 4; mt++) {
            const size_t tok0 = (size_t)mi * 256 + warp * 64 + mt * 16;
            #pragma unroll
            for (int hf = 0; hf < 2; hf++) {
                const int lo = hf * 2;
                float s = 0.f;
                #pragma unroll
                for (int nt = 0; nt < 7; nt++)
                    s += acc[mt][nt][lo] + acc[mt][nt][lo + 1];
                #pragma unroll
                for (int o = 16; o > 0; o >>= 1)
                    s += __shfl_xor_sync(0xffffffffu, s, o);
                const float mu = s * (1.f / 448.f);
                float vs = 0.f;
                #pragma unroll
                for (int nt = 0; nt < 7; nt++) {
                    float d0 = acc[mt][nt][lo] - mu;
                    float d1 = acc[mt][nt][lo + 1] - mu;
                    vs += d0 * d0 + d1 * d1;
                }
                #pragma unroll
                for (int o = 16; o > 0; o >>= 1)
                    vs += __shfl_xor_sync(0xffffffffu, vs, o);
                const float rsig = rsqrtf(vs * (1.f / 448.f) + 1e-5f);

                const size_t tok = tok0 + hf * 8;
                const size_t R = (tok >> 13) * SEQ + (size_t)hh * 1024
                               + ((tok & 8191) >> 3);
                const uint32_t mi_o = (uint32_t)(R >> 8), rt = (uint32_t)R & 255;
                const uint32_t rpart = mi_o * 229376u
                                     + (rt >> 6) * 8192u
                                     + (((rt >> 4) & 3) * 512u)
                                     + ((rt & 7) * 64u)
                                     + (((rt >> 3) & 1) * 4u);
                char* yb = (char*)Og;
                #pragma unroll
                for (int nt = 0; nt < 7; nt++) {
                    const int c = g * 56 + nt * 8 + 2 * li;
                    const uint32_t cpart = (uint32_t)(c >> 6) * 32768u
                                         + (uint32_t)((c >> 4) & 3) * 2048u
                                         + (uint32_t)((c >> 2) & 3) * 16u
                                         + (uint32_t)((c & 2) << 2);
                    *(__half2*)(yb + rpart + cpart) = __floats2half2_rn(
                        (acc[mt][nt][lo]     - mu) * rsig * g1[c]     + g2[c],
                        (acc[mt][nt][lo + 1] - mu) * rsig * g1[c + 1] + g2[c + 1]);
                }
            }
        }
        #pragma unroll
        for (int mt = 0; mt < 4; mt++)
            #pragma unroll
            for (int nt = 0; nt < 7; nt++)
                #pragma unroll
                for (int r = 0; r < 4; r++) acc[mt][nt][r] = 0.f;
        mi += NSLOT;
    }
}

// ============================================================================
// GEMM2: out = Yn[blob] @ W^T + bias (f32 out). Same as R14 LN=false path.
// ============================================================================
__global__ __launch_bounds__(128, 2) void gemm2_blob(
    const uint4* __restrict__ Ab,    // Yn fragment blob
    const __half* __restrict__ Bg,   // W [448,448] row-major [n,k] fp16
    float* __restrict__ Cg,          // [65536,448] f32
    const float* __restrict__ g1)    // bias
{
    extern __shared__ char sm[];
    const uint32_t sb = smem_u32(sm);
    const int tid  = threadIdx.x;
    const int warp = tid >> 5, lane = tid & 31;
    const int g  = lane >> 2, li = lane & 3;
    const int hh   = blockIdx.x & 7;
    const int slot = blockIdx.x >> 3;
    const int N0 = hh * HD;
    const int ntile = (slot + NSLOT * 6 < MTILES) ? 7 : 6;

    uint32_t brow[7], swk[4];
    #pragma unroll
    for (int nt = 0; nt < 7; nt++) brow[nt] = (uint32_t)((nt * 8 + g) * 128);
    #pragma unroll
    for (int kk = 0; kk < 4; kk++)
        swk[kk] = (uint32_t)((((2 * kk + (li >> 1)) ^ g) << 4) | ((li & 1) << 3));

    #pragma unroll
    for (int j = 0; j < 25; j++) {
        int o = tid + 128 * j;
        if (o < NKT * HD * 8) {
            int kt = o / (HD * 8), rem = o % (HD * 8);
            int row = rem >> 3, c2 = rem & 7;
            CP_ASYNC16(sb + kt * B_CHUNK + (uint32_t)row * 128
                           + ((uint32_t)((c2 ^ (row & 7)) << 4)),
                       Bg + (size_t)(N0 + row) * DIN + (size_t)kt * GBK + c2 * 8);
        }
    }
    CP_COMMIT();

    uint4 frag[4][4];
    {
        const uint4* ap = Ab + ((size_t)(slot * 7 + 0) * 16 + warp * 4) * 128 + lane;
        #pragma unroll
        for (int kk = 0; kk < 4; kk++)
            #pragma unroll
            for (int mt = 0; mt < 4; mt++)
                frag[kk][mt] = ap[kk * 128 + mt * 32];
    }

    CP_WAIT0();
    __syncthreads();

    float acc[4][7][4];
    #pragma unroll
    for (int mt = 0; mt < 4; mt++)
        #pragma unroll
        for (int nt = 0; nt < 7; nt++)
            #pragma unroll
            for (int r = 0; r < 4; r++) acc[mt][nt][r] = 0.f;

    int mi = slot;
    for (int ti = 0; ti < ntile; ti++) {
        for (int kt = 0; kt < NKT; kt++) {
            const char* sbp = sm + kt * B_CHUNK;
            const bool more = (kt < NKT - 1) || (ti < ntile - 1);
            const int nmi = (kt < NKT - 1) ? mi : mi + NSLOT;
            const int nkt = (kt < NKT - 1) ? kt + 1 : 0;
            const uint4* anx = Ab + ((size_t)(nmi * 7 + nkt) * 16 + warp * 4) * 128 + lane;

            {
                int p2mi, p2kt;
                bool pok = true;
                if (kt + 2 < NKT)        { p2mi = mi;         p2kt = kt + 2; }
                else if (ti + 1 < ntile) { p2mi = mi + NSLOT; p2kt = kt + 2 - NKT; }
                else                     { p2mi = mi; p2kt = 0; pok = false; }
                if (pok) {
                    const char* pfp = (const char*)(Ab
                        + ((size_t)(p2mi * 7 + p2kt) * 16 + warp * 4) * 128)
                        + (uint32_t)lane * 256;
                    PREFETCH_L2(pfp);
                    PREFETCH_L2(pfp + 128);
                }
            }

            #pragma unroll
            for (int kk = 0; kk < 4; kk++) {
                const uint32_t sw = swk[kk];
                uint2 bv[7];
                #pragma unroll
                for (int nt = 0; nt < 7; nt++)
                    bv[nt] = *(const uint2*)(sbp + brow[nt] + sw);
                #pragma unroll
                for (int mt = 0; mt < 4; mt++) {
                    const uint4 a = frag[kk][mt];
                    #pragma unroll
                    for (int nt = 0; nt < 7; nt++)
                        MMA_FP16(acc[mt][nt], a, bv[nt]);
                }
                if (more) {
                    #pragma unroll
                    for (int mt = 0; mt < 4; mt++)
                        frag[kk][mt] = anx[kk * 128 + mt * 32];
                }
            }
        }

        #pragma unroll
        for (int mt = 0; mt < 4; mt++) {
            const size_t r0 = (size_t)mi * 256 + warp * 64 + mt * 16 + g;
            #pragma unroll
            for (int nt = 0; nt < 7; nt++) {
                const int c0 = N0 + nt * 8 + 2 * li;
                const float2 bb = *(const float2*)&g1[c0];
                *(float2*)&Cg[r0 * DIN + c0] =
                    make_float2(acc[mt][nt][0] + bb.x, acc[mt][nt][1] + bb.y);
                *(float2*)&Cg[(r0 + 8) * DIN + c0] =
                    make_float2(acc[mt][nt][2] + bb.x, acc[mt][nt][3] + bb.y);
            }
        }
        #pragma unroll
        for (int mt = 0; mt < 4; mt++)
            #pragma unroll
            for (int nt = 0; nt < 7; nt++)
                #pragma unroll
                for (int r = 0; r < 4; r++) acc[mt][nt][r] = 0.f;
        mi += NSLOT;
    }
}

// ---------------- f32 -> fp16 linear conversion (for W) --------------------
__global__ void conv_h(const float4* __restrict__ src, __half2* __restrict__ dst, int n4) {
    int i = blockIdx.x * blockDim.x + threadIdx.x;
    if (i < n4) {
        float4 v = src[i];
        dst[2 * i]     = __floats2half2_rn(v.x, v.y);
        dst[2 * i + 1] = __floats2half2_rn(v.z, v.w);
    }
}

// ---------------- E_h = C_h * M^T * A_h^T * B_h  (-> fp16) -----------------
__global__ void computeE_k(const float* __restrict__ A, const float* __restrict__ B,
                           const float* __restrict__ C) {
    __shared__ float G[HD * HD], Cs[HD * HD], F[7 * HD];
    const int h = blockIdx.x, oc = blockIdx.y;
    const int tid = threadIdx.x;     // 448 threads
    for (int i = tid; i < HD * HD; i += 448) {
        G[i]  = A[h * HD * HD + i];
        Cs[i] = C[h * HD * HD + i];
    }
    __syncthreads();
    if (tid < HD) {
        #pragma unroll
        for (int e = HD - 2; e >= 0; e--) G[tid * HD + e] += G[tid * HD + e + 1];
    }
    __syncthreads();
    if (tid < 7 * HD) {
        int ol = tid / HD, d = tid % HD;
        float s = 0.f;
        #pragma unroll
        for (int e = 0; e < HD; e++) s += Cs[(oc * 7 + ol) * HD + e] * G[d * HD + e];
        F[ol * HD + d] = s;
    }
    __syncthreads();
    const int i = tid;
    float acc[7] = {0, 0, 0, 0, 0, 0, 0};
    for (int d = 0; d < HD; d++) {
        float b = B[(size_t)(h * HD + d) * DIN + i];
        #pragma unroll
        for (int ol = 0; ol < 7; ol++) acc[ol] += F[ol * HD + d] * b;
    }
    #pragma unroll
    for (int ol = 0; ol < 7; ol++)
        Eh_g[(size_t)(h * HD + oc * 7 + ol) * DIN + i] = __float2half_rn(acc[ol]);
}

// ---------------------------------------------------------------------------
extern "C" void kernel_launch(void* const* d_in, const int* in_sizes, int n_in,
                              void* d_out, int out_size) {
    const float* x     = (const float*)d_in[0];
    const float* A     = (const float*)d_in[1];
    const float* B     = (const float*)d_in[2];
    const float* C     = (const float*)d_in[3];
    const float* gamma = (const float*)d_in[4];
    const float* beta  = (const float*)d_in[5];
    const float* W     = (const float*)d_in[6];
    const float* bias  = (const float*)d_in[7];
    float* out = (float*)d_out;

    __half *Eh_p, *Wh_p;
    uint4 *Yb_p;
    cudaGetSymbolAddress((void**)&Eh_p, Eh_g);
    cudaGetSymbolAddress((void**)&Wh_p, Wh_g);
    cudaGetSymbolAddress((void**)&Yb_p, Yb_g);

    cudaFuncSetAttribute(gemm1_f32,
                         cudaFuncAttributeMaxDynamicSharedMemorySize, GSMEM);
    cudaFuncSetAttribute(gemm2_blob,
                         cudaFuncAttributeMaxDynamicSharedMemorySize, GSMEM);

    conv_h<<<196, 256>>>((const float4*)W, (__half2*)Wh_p, 50176);
    computeE_k<<<dim3(HEADS, 8), DIN>>>(A, B, C);

    // GEMM1 (+convert +LN, permuted) : x(f32) @ E^T -> Yn blob
    gemm1_f32<<<HEADS * NSLOT, 128, GSMEM>>>(x, Eh_p, Yb_p, gamma, beta);
    // GEMM2 (+bias)                  : Yn-blob @ W^T -> out (f32)
    gemm2_blob<<<HEADS * NSLOT, 128, GSMEM>>>(Yb_p, Wh_p, out, bias);
}

// round 17
// speedup vs baseline: 1.0026x; 1.0026x over previous
#include <cuda_runtime.h>
#include <cuda_fp16.h>
#include <cstdint>

#define DIN 448
#define HEADS 8
#define HD 56
#define SEQ 8192
#define TOKENS 65536
#define NSLOT 37                      // CTAs per head; grid = 8*37 = 296 = 2/SM
#define NCTA  (HEADS * NSLOT)         // 296 — one full wave at 2 CTAs/SM
#define MTILES 256                    // 65536 / 256
#define NKT    7                      // 448 / 64
#define GBK    64                     // k-tile depth (halves)
#define NUNITS (TOKENS * DIN / 8)     // 3,670,016 blob units

// ---------------- scratch (device globals; no runtime alloc) ---------------
__device__ __half Eh_g[DIN * DIN];
__device__ __half Wh_g[DIN * DIN];
__device__ uint4  Xb_g[(size_t)NUNITS];   // x  blob (fp16)
__device__ uint4  Yb_g[(size_t)NUNITS];   // Yn blob (fp16)
__device__ unsigned bar_cnt_g;            // monotonic grid-barrier ticket
__device__ unsigned bar_rel_g;            // monotonic release counter

// Blob mapping for a [rows, 448] fp16 matrix:
//   row: mi=row>>8, rt=row&255, w=rt>>6, mt=(rt>>4)&3, hi=(rt>>3)&1, g=rt&7
//   col: kt=col>>6, kk=(col>>4)&3, li=(col>>2)&3, p=col&3
//   uint4 index = ((mi*7+kt)*16 + w*4 + kk)*128 + mt*32 + g*4 + li
//   16B unit = MMA regs {a0,a1,a2,a3} under the phys-col relabel
//   hw{2li,2li+1}->4li,4li+1 ; hw{2li+8,2li+9}->4li+2,4li+3.

// ---------------- helpers --------------------------------------------------
#define CP_ASYNC16(dst, src) \
    asm volatile("cp.async.cg.shared.global [%0], [%1], 16;" :: "r"(dst), "l"(src) : "memory")
#define CP_COMMIT() asm volatile("cp.async.commit_group;" ::: "memory")
#define CP_WAIT0()  asm volatile("cp.async.wait_group 0;" ::: "memory")
#define PREFETCH_L2(p) \
    asm volatile("prefetch.global.L2 [%0];" :: "l"(p))

__device__ __forceinline__ uint32_t smem_u32(const void* p) {
    uint32_t a;
    asm("{ .reg .u64 t; cvta.to.shared.u64 t, %1; cvt.u32.u64 %0, t; }"
        : "=r"(a) : "l"(p));
    return a;
}

#define B_CHUNK (HD * 128)               // 7168 per k-tile
#define GSMEM   (NKT * B_CHUNK)          // 50176
#define KT_U4   2048                     // uint4 per (mi,kt) blob block

#define MMA_FP16(acc, a, bv)                                                  \
    asm volatile(                                                             \
        "mma.sync.aligned.m16n8k16.row.col.f32.f16.f16.f32 "                  \
        "{%0,%1,%2,%3}, {%4,%5,%6,%7}, {%8,%9}, {%0,%1,%2,%3};\n"             \
        : "+f"((acc)[0]), "+f"((acc)[1]), "+f"((acc)[2]), "+f"((acc)[3])      \
        : "r"((a).x), "r"((a).y), "r"((a).z), "r"((a).w),                     \
          "r"((bv).x), "r"((bv).y))

// Monotonic-epoch grid barrier. Safe: grid == one resident wave (296 CTAs,
// 2/SM enforced by __launch_bounds__). Counters only increase -> replay-safe
// under CUDA-graph timing loops.
__device__ __forceinline__ void gridbar() {
    __threadfence();
    __syncthreads();
    if (threadIdx.x == 0) {
        unsigned ticket = atomicAdd(&bar_cnt_g, 1u);
        unsigned epoch  = ticket / (unsigned)NCTA;
        if ((ticket % (unsigned)NCTA) == (unsigned)(NCTA - 1)) {
            atomicAdd(&bar_rel_g, 1u);
        } else {
            while (*(volatile unsigned*)&bar_rel_g <= epoch) { }
        }
    }
    __syncthreads();
    __threadfence();
}

// ---------------- one persistent GEMM phase (R14-proven mainloop) ----------
// A in fragment blob (LDG.128 -> regs, depth-4 ring), B panel resident in
// smem, warp tile 64x56, m16n8k16, L2 prefetch t+2, barrier-free mainloop.
template<bool LN>
__device__ __forceinline__ void gemm_phase(
    const uint4* __restrict__ Ab, const __half* __restrict__ Bg,
    void* __restrict__ Og, const float* __restrict__ g1,
    const float* __restrict__ g2,
    char* sm, uint32_t sb, int tid, int warp, int lane, int g, int li,
    int hh, int slot, int N0, int ntile)
{
    uint32_t brow[7], swk[4];
    #pragma unroll
    for (int nt = 0; nt < 7; nt++) brow[nt] = (uint32_t)((nt * 8 + g) * 128);
    #pragma unroll
    for (int kk = 0; kk < 4; kk++)
        swk[kk] = (uint32_t)((((2 * kk + (li >> 1)) ^ g) << 4) | ((li & 1) << 3));

    // ---- B panel -> smem ----
    #pragma unroll
    for (int j = 0; j < 25; j++) {
        int o = tid + 128 * j;
        if (o < NKT * HD * 8) {
            int kt = o / (HD * 8), rem = o % (HD * 8);
            int row = rem >> 3, c2 = rem & 7;
            CP_ASYNC16(sb + kt * B_CHUNK + (uint32_t)row * 128
                           + ((uint32_t)((c2 ^ (row & 7)) << 4)),
                       Bg + (size_t)(N0 + row) * DIN + (size_t)kt * GBK + c2 * 8);
        }
    }
    CP_COMMIT();

    // ---- prologue: first k-tile's A fragments (ring slot = kk) ----
    uint4 frag[4][4];
    {
        const uint4* ap = Ab + ((size_t)(slot * 7 + 0) * 16 + warp * 4) * 128 + lane;
        #pragma unroll
        for (int kk = 0; kk < 4; kk++)
            #pragma unroll
            for (int mt = 0; mt < 4; mt++)
                frag[kk][mt] = ap[kk * 128 + mt * 32];
    }

    CP_WAIT0();
    __syncthreads();                      // B visible

    float acc[4][7][4];
    #pragma unroll
    for (int mt = 0; mt < 4; mt++)
        #pragma unroll
        for (int nt = 0; nt < 7; nt++)
            #pragma unroll
            for (int r = 0; r < 4; r++) acc[mt][nt][r] = 0.f;

    int mi = slot;
    for (int ti = 0; ti < ntile; ti++) {
        for (int kt = 0; kt < NKT; kt++) {
            const char* sbp = sm + kt * B_CHUNK;
            const bool more = (kt < NKT - 1) || (ti < ntile - 1);
            const int nmi = (kt < NKT - 1) ? mi : mi + NSLOT;
            const int nkt = (kt < NKT - 1) ? kt + 1 : 0;
            const uint4* anx = Ab + ((size_t)(nmi * 7 + nkt) * 16 + warp * 4) * 128 + lane;

            {   // L2 prefetch: this warp's A segment of k-tile t+2
                int p2mi, p2kt;
                bool pok = true;
                if (kt + 2 < NKT)        { p2mi = mi;         p2kt = kt + 2; }
                else if (ti + 1 < ntile) { p2mi = mi + NSLOT; p2kt = kt + 2 - NKT; }
                else                     { p2mi = mi; p2kt = 0; pok = false; }
                if (pok) {
                    const char* pfp = (const char*)(Ab
                        + ((size_t)(p2mi * 7 + p2kt) * 16 + warp * 4) * 128)
                        + (uint32_t)lane * 256;
                    PREFETCH_L2(pfp);
                    PREFETCH_L2(pfp + 128);
                }
            }

            #pragma unroll
            for (int kk = 0; kk < 4; kk++) {
                const uint32_t sw = swk[kk];
                uint2 bv[7];
                #pragma unroll
                for (int nt = 0; nt < 7; nt++)
                    bv[nt] = *(const uint2*)(sbp + brow[nt] + sw);
                #pragma unroll
                for (int mt = 0; mt < 4; mt++) {
                    const uint4 a = frag[kk][mt];
                    #pragma unroll
                    for (int nt = 0; nt < 7; nt++)
                        MMA_FP16(acc[mt][nt], a, bv[nt]);
                }
                if (more) {
                    #pragma unroll
                    for (int mt = 0; mt < 4; mt++)
                        frag[kk][mt] = anx[kk * 128 + mt * 32];
                }
            }
        }

        // ---- epilogue for m-tile mi ----
        if (LN) {
            #pragma unroll
            for (int mt = 0; mt < 4; mt++) {
                const size_t tok0 = (size_t)mi * 256 + warp * 64 + mt * 16;
                #pragma unroll
                for (int hf = 0; hf < 2; hf++) {
                    const int lo = hf * 2;
                    float s = 0.f;
                    #pragma unroll
                    for (int nt = 0; nt < 7; nt++)
                        s += acc[mt][nt][lo] + acc[mt][nt][lo + 1];
                    #pragma unroll
                    for (int o = 16; o > 0; o >>= 1)
                        s += __shfl_xor_sync(0xffffffffu, s, o);
                    const float mu = s * (1.f / 448.f);
                    float vs = 0.f;
                    #pragma unroll
                    for (int nt = 0; nt < 7; nt++) {
                        float d0 = acc[mt][nt][lo] - mu;
                        float d1 = acc[mt][nt][lo + 1] - mu;
                        vs += d0 * d0 + d1 * d1;
                    }
                    #pragma unroll
                    for (int o = 16; o > 0; o >>= 1)
                        vs += __shfl_xor_sync(0xffffffffu, vs, o);
                    const float rsig = rsqrtf(vs * (1.f / 448.f) + 1e-5f);

                    const size_t tok = tok0 + hf * 8;
                    const size_t R = (tok >> 13) * SEQ + (size_t)hh * 1024
                                   + ((tok & 8191) >> 3);
                    const uint32_t mi_o = (uint32_t)(R >> 8), rt = (uint32_t)R & 255;
                    const uint32_t rpart = mi_o * 229376u
                                         + (rt >> 6) * 8192u
                                         + (((rt >> 4) & 3) * 512u)
                                         + ((rt & 7) * 64u)
                                         + (((rt >> 3) & 1) * 4u);
                    char* yb = (char*)Og;
                    #pragma unroll
                    for (int nt = 0; nt < 7; nt++) {
                        const int c = g * 56 + nt * 8 + 2 * li;
                        const uint32_t cpart = (uint32_t)(c >> 6) * 32768u
                                             + (uint32_t)((c >> 4) & 3) * 2048u
                                             + (uint32_t)((c >> 2) & 3) * 16u
                                             + (uint32_t)((c & 2) << 2);
                        *(__half2*)(yb + rpart + cpart) = __floats2half2_rn(
                            (acc[mt][nt][lo]     - mu) * rsig * g1[c]     + g2[c],
                            (acc[mt][nt][lo + 1] - mu) * rsig * g1[c + 1] + g2[c + 1]);
                    }
                }
            }
        } else {
            float* Cg = (float*)Og;
            #pragma unroll
            for (int mt = 0; mt < 4; mt++) {
                const size_t r0 = (size_t)mi * 256 + warp * 64 + mt * 16 + g;
                #pragma unroll
                for (int nt = 0; nt < 7; nt++) {
                    const int c0 = N0 + nt * 8 + 2 * li;
                    const float2 bb = *(const float2*)&g1[c0];
                    *(float2*)&Cg[r0 * DIN + c0] =
                        make_float2(acc[mt][nt][0] + bb.x, acc[mt][nt][1] + bb.y);
                    *(float2*)&Cg[(r0 + 8) * DIN + c0] =
                        make_float2(acc[mt][nt][2] + bb.x, acc[mt][nt][3] + bb.y);
                }
            }
        }
        #pragma unroll
        for (int mt = 0; mt < 4; mt++)
            #pragma unroll
            for (int nt = 0; nt < 7; nt++)
                #pragma unroll
                for (int r = 0; r < 4; r++) acc[mt][nt][r] = 0.f;
        mi += NSLOT;
    }
}

// ============================================================================
// The persistent fused kernel: phase0 conv(x->blob) | bar | GEMM1+LN | bar |
// GEMM2+bias. Grid = 296 = one resident wave.
// ============================================================================
__global__ __launch_bounds__(128, 2) void fused_all(
    const float* __restrict__ X,
    const __half* __restrict__ Eh,
    const __half* __restrict__ Wh,
    uint4* __restrict__ Xb,
    uint4* __restrict__ Yb,
    float* __restrict__ Out,
    const float* __restrict__ gamma,
    const float* __restrict__ beta,
    const float* __restrict__ bias)
{
    extern __shared__ char sm[];
    const uint32_t sb = smem_u32(sm);
    const int tid  = threadIdx.x;
    const int warp = tid >> 5, lane = tid & 31;
    const int g  = lane >> 2, li = lane & 3;
    const int hh   = blockIdx.x & 7;
    const int slot = blockIdx.x >> 3;
    const int N0 = hh * HD;
    const int ntile = (slot + NSLOT * 6 < MTILES) ? 7 : 6;

    // ---- phase 0: x (f32) -> fragment blob (fp16), grid-stride ----
    for (int id = blockIdx.x * 128 + tid; id < NUNITS; id += NCTA * 128) {
        const int ln2 = id & 31, li2 = ln2 & 3, gg = ln2 >> 2;
        const int mt = (id >> 5) & 3, kk = (id >> 7) & 3, w = (id >> 9) & 3;
        const int ktmi = id >> 11;
        const int mi = ktmi / 7, kt = ktmi - mi * 7;
        const int r0 = mi * 256 + w * 64 + mt * 16 + gg;
        const int c0 = kt * 64 + kk * 16 + li2 * 4;
        const float4 v0 = *(const float4*)(X + (size_t)r0 * DIN + c0);
        const float4 v1 = *(const float4*)(X + (size_t)(r0 + 8) * DIN + c0);
        __half2 h0 = __floats2half2_rn(v0.x, v0.y);
        __half2 h1 = __floats2half2_rn(v1.x, v1.y);
        __half2 h2 = __floats2half2_rn(v0.z, v0.w);
        __half2 h3 = __floats2half2_rn(v1.z, v1.w);
        uint4 o;
        o.x = *(uint32_t*)&h0; o.y = *(uint32_t*)&h1;
        o.z = *(uint32_t*)&h2; o.w = *(uint32_t*)&h3;
        Xb[id] = o;
    }

    gridbar();                 // Xb complete

    // ---- phase 1: GEMM1 + LayerNorm (permuted) -> Yn blob ----
    gemm_phase<true>(Xb, Eh, (void*)Yb, gamma, beta,
                     sm, sb, tid, warp, lane, g, li, hh, slot, N0, ntile);

    gridbar();                 // Yb complete

    // ---- phase 2: GEMM2 + bias -> f32 out ----
    gemm_phase<false>(Yb, Wh, (void*)Out, bias, nullptr,
                      sm, sb, tid, warp, lane, g, li, hh, slot, N0, ntile);
}

// ---------------- f32 -> fp16 linear conversion (for W) --------------------
__global__ void conv_h(const float4* __restrict__ src, __half2* __restrict__ dst, int n4) {
    int i = blockIdx.x * blockDim.x + threadIdx.x;
    if (i < n4) {
        float4 v = src[i];
        dst[2 * i]     = __floats2half2_rn(v.x, v.y);
        dst[2 * i + 1] = __floats2half2_rn(v.z, v.w);
    }
}

// ---------------- E_h = C_h * M^T * A_h^T * B_h  (-> fp16) -----------------
__global__ void computeE_k(const float* __restrict__ A, const float* __restrict__ B,
                           const float* __restrict__ C) {
    __shared__ float G[HD * HD], Cs[HD * HD], F[7 * HD];
    const int h = blockIdx.x, oc = blockIdx.y;
    const int tid = threadIdx.x;     // 448 threads
    for (int i = tid; i < HD * HD; i += 448) {
        G[i]  = A[h * HD * HD + i];
        Cs[i] = C[h * HD * HD + i];
    }
    __syncthreads();
    if (tid < HD) {
        #pragma unroll
        for (int e = HD - 2; e >= 0; e--) G[tid * HD + e] += G[tid * HD + e + 1];
    }
    __syncthreads();
    if (tid < 7 * HD) {
        int ol = tid / HD, d = tid % HD;
        float s = 0.f;
        #pragma unroll
        for (int e = 0; e < HD; e++) s += Cs[(oc * 7 + ol) * HD + e] * G[d * HD + e];
        F[ol * HD + d] = s;
    }
    __syncthreads();
    const int i = tid;
    float acc[7] = {0, 0, 0, 0, 0, 0, 0};
    for (int d = 0; d < HD; d++) {
        float b = B[(size_t)(h * HD + d) * DIN + i];
        #pragma unroll
        for (int ol = 0; ol < 7; ol++) acc[ol] += F[ol * HD + d] * b;
    }
    #pragma unroll
    for (int ol = 0; ol < 7; ol++)
        Eh_g[(size_t)(h * HD + oc * 7 + ol) * DIN + i] = __float2half_rn(acc[ol]);
}

// ---------------------------------------------------------------------------
extern "C" void kernel_launch(void* const* d_in, const int* in_sizes, int n_in,
                              void* d_out, int out_size) {
    const float* x     = (const float*)d_in[0];
    const float* A     = (const float*)d_in[1];
    const float* B     = (const float*)d_in[2];
    const float* C     = (const float*)d_in[3];
    const float* gamma = (const float*)d_in[4];
    const float* beta  = (const float*)d_in[5];
    const float* W     = (const float*)d_in[6];
    const float* bias  = (const float*)d_in[7];
    float* out = (float*)d_out;

    __half *Eh_p, *Wh_p;
    uint4 *Xb_p, *Yb_p;
    cudaGetSymbolAddress((void**)&Eh_p, Eh_g);
    cudaGetSymbolAddress((void**)&Wh_p, Wh_g);
    cudaGetSymbolAddress((void**)&Xb_p, Xb_g);
    cudaGetSymbolAddress((void**)&Yb_p, Yb_g);

    cudaFuncSetAttribute(fused_all,
                         cudaFuncAttributeMaxDynamicSharedMemorySize, GSMEM);

    conv_h<<<196, 256>>>((const float4*)W, (__half2*)Wh_p, 50176);
    computeE_k<<<dim3(HEADS, 8), DIN>>>(A, B, C);

    fused_all<<<NCTA, 128, GSMEM>>>(x, Eh_p, Wh_p, Xb_p, Yb_p, out,
                                    gamma, beta, bias);
}